// round 8
// baseline (speedup 1.0000x reference)
#include <cuda_runtime.h>
#include <cuda_bf16.h>
#include <cstdint>

// QuadraticNetCholesky, R7: two kernels.
//  A: MLP via mma.sync bf16x3 (unchanged from R6, ~52us), writes L
//     (softplus out, 78+2 floats) into out[s*144+0..79].
//  B: REBUILT. Zero-padded 12x12 L in smem -> uniform 12-deep dots,
//     4 lanes/sample x 3 rows, 8 samples/warp, 20 warps/SM.

#define NIN 12
#define NTILE 68

typedef unsigned int u32;

// ---- kernel A smem (bytes) ----
#define O_FRAG 0                       // 68 tiles x 32 lanes x 16B = 34816
#define O_B2   34816                   // 32 f32
#define O_B3   34944                   // 80 f32
#define SMEM_A (34944 + 320)           // 35264

__device__ __forceinline__ u32 pack_bf16x2(float e0, float e1) {  // e0 -> low half
    u32 d;
    asm("cvt.rn.bf16x2.f32 %0, %1, %2;" : "=r"(d) : "f"(e1), "f"(e0));
    return d;
}
__device__ __forceinline__ void split2(float f0, float f1, u32& hi, u32& lo) {
    hi = pack_bf16x2(f0, f1);
    float h0 = __uint_as_float(hi << 16);
    float h1 = __uint_as_float(hi & 0xffff0000u);
    lo = pack_bf16x2(f0 - h0, f1 - h1);
}
__device__ __forceinline__ float elu_f(float p) { return p > 0.f ? p : (__expf(p) - 1.f); }
__device__ __forceinline__ float softp(float t) {
    return fmaxf(t, 0.f) + __logf(1.f + __expf(-fabsf(t)));
}

__device__ __forceinline__ void mma16816(float* d, u32 a0, u32 a1, u32 a2, u32 a3,
                                         u32 b0, u32 b1) {
    asm volatile(
        "mma.sync.aligned.m16n8k16.row.col.f32.bf16.bf16.f32 "
        "{%0,%1,%2,%3},{%4,%5,%6,%7},{%8,%9},{%0,%1,%2,%3};"
        : "+f"(d[0]), "+f"(d[1]), "+f"(d[2]), "+f"(d[3])
        : "r"(a0), "r"(a1), "r"(a2), "r"(a3), "r"(b0), "r"(b1));
}
__device__ __forceinline__ void mma3(float* d, const u32* ah, const u32* al, uint4 f) {
    mma16816(d, ah[0], ah[1], ah[2], ah[3], f.x, f.y);   // hi*hi
    mma16816(d, ah[0], ah[1], ah[2], ah[3], f.z, f.w);   // hi*lo
    mma16816(d, al[0], al[1], al[2], al[3], f.x, f.y);   // lo*hi
}

// =============================== Kernel A ===============================
__global__ void __launch_bounds__(256, 3)
qnc_mlp_kernel(const float* __restrict__ x,
               const float* __restrict__ W1, const float* __restrict__ b1,
               const float* __restrict__ W2, const float* __restrict__ b2,
               const float* __restrict__ W3, const float* __restrict__ b3,
               float* __restrict__ out, int ntiles)
{
    extern __shared__ char sm[];
    float* smf = reinterpret_cast<float*>(sm);
    const int tid  = threadIdx.x;
    const int lane = tid & 31;
    const int w    = tid >> 5;
    const int g    = lane >> 2;
    const int tq   = lane & 3;

    // ---- stage weights once per CTA in fragment order ----
    for (int idx = tid; idx < NTILE * 32; idx += 256) {
        const int t  = idx >> 5;
        const int l2 = idx & 31;
        const int g2 = l2 >> 2, tq2 = l2 & 3;
        float v0, v1, v2, v3;
        if (t < 16) {                         // W1[128][12] + b1 as K-col 12
            const int n = 8 * t + g2;
            const float* r = W1 + n * NIN;
            v0 = r[2 * tq2]; v1 = r[2 * tq2 + 1];
            const int k2 = 8 + 2 * tq2;
            v2 = (k2 < NIN) ? r[k2] : ((k2 == 12) ? b1[n] : 0.f);
            v3 = (k2 + 1 < NIN) ? r[k2 + 1] : ((k2 + 1 == 12) ? b1[n] : 0.f);
        } else if (t < 48) {                  // W2[32][128]
            const int tt = t - 16, s = tt >> 2, j = tt & 3;
            const float* r = W2 + (8 * j + g2) * 128 + 16 * s;
            v0 = r[2 * tq2]; v1 = r[2 * tq2 + 1];
            v2 = r[8 + 2 * tq2]; v3 = r[9 + 2 * tq2];
        } else {                              // W3[78][32], rows 78,79 = 0
            const int tt = t - 48, s = tt / 10, j = tt - 10 * s;
            const int n = 8 * j + g2;
            if (n < 78) {
                const float* r = W3 + n * 32 + 16 * s;
                v0 = r[2 * tq2]; v1 = r[2 * tq2 + 1];
                v2 = r[8 + 2 * tq2]; v3 = r[9 + 2 * tq2];
            } else {
                v0 = v1 = v2 = v3 = 0.f;
            }
        }
        u32 h0, l0, h1, l1;
        split2(v0, v1, h0, l0);
        split2(v2, v3, h1, l1);
        *reinterpret_cast<uint4*>(sm + O_FRAG + t * 512 + l2 * 16) =
            make_uint4(h0, h1, l0, l1);
    }
    for (int i = tid; i < 32; i += 256) smf[O_B2 / 4 + i] = b2[i];
    for (int i = tid; i < 80; i += 256) smf[O_B3 / 4 + i] = (i < 78) ? b3[i] : 0.f;
    __syncthreads();

    const uint4* frag = reinterpret_cast<const uint4*>(sm + O_FRAG) + lane;

    for (int tile = blockIdx.x; tile < ntiles; tile += gridDim.x) {
        const int warp_s0 = tile * 128 + w * 16;

        // A1 fragments from x
        const float* xr  = x + (size_t)(warp_s0 + g) * NIN;
        const float* xr8 = xr + 8 * NIN;
        float2 xa = *reinterpret_cast<const float2*>(xr  + 2 * tq);
        float2 xb = *reinterpret_cast<const float2*>(xr8 + 2 * tq);
        float2 xc, xd;
        if (tq < 2) {
            xc = *reinterpret_cast<const float2*>(xr  + 8 + 2 * tq);
            xd = *reinterpret_cast<const float2*>(xr8 + 8 + 2 * tq);
        } else {
            float one = (tq == 2) ? 1.f : 0.f;    // bias col 12
            xc = make_float2(one, 0.f);
            xd = make_float2(one, 0.f);
        }
        u32 a1h[4], a1l[4];
        split2(xa.x, xa.y, a1h[0], a1l[0]);
        split2(xb.x, xb.y, a1h[1], a1l[1]);
        split2(xc.x, xc.y, a1h[2], a1l[2]);
        split2(xd.x, xd.y, a1h[3], a1l[3]);

        // fused GEMM1 -> elu -> GEMM2, one k-step (16 h1 neurons) at a time
        float acc2[4][4];
#pragma unroll
        for (int j = 0; j < 4; j++) acc2[j][0] = acc2[j][1] = acc2[j][2] = acc2[j][3] = 0.f;
#pragma unroll
        for (int s = 0; s < 8; s++) {
            float p[8];
#pragma unroll
            for (int q = 0; q < 8; q++) p[q] = 0.f;
            mma3(p,     a1h, a1l, frag[(2 * s) * 32]);
            mma3(p + 4, a1h, a1l, frag[(2 * s + 1) * 32]);
            u32 a2h4[4], a2l4[4];
            split2(elu_f(p[0]), elu_f(p[1]), a2h4[0], a2l4[0]);
            split2(elu_f(p[2]), elu_f(p[3]), a2h4[1], a2l4[1]);
            split2(elu_f(p[4]), elu_f(p[5]), a2h4[2], a2l4[2]);
            split2(elu_f(p[6]), elu_f(p[7]), a2h4[3], a2l4[3]);
#pragma unroll
            for (int j = 0; j < 4; j++)
                mma3(acc2[j], a2h4, a2l4, frag[(16 + 4 * s + j) * 32]);
        }

        // epi2: +b2, elu -> A3 fragments
        float h2e[16];
#pragma unroll
        for (int j = 0; j < 4; j++) {
            float2 bb = *reinterpret_cast<const float2*>(smf + O_B2 / 4 + 8 * j + 2 * tq);
            h2e[4 * j + 0] = elu_f(acc2[j][0] + bb.x);
            h2e[4 * j + 1] = elu_f(acc2[j][1] + bb.y);
            h2e[4 * j + 2] = elu_f(acc2[j][2] + bb.x);
            h2e[4 * j + 3] = elu_f(acc2[j][3] + bb.y);
        }
        u32 a3h[2][4], a3l[2][4];
#pragma unroll
        for (int s = 0; s < 2; s++) {
            split2(h2e[8 * s + 0], h2e[8 * s + 1], a3h[s][0], a3l[s][0]);
            split2(h2e[8 * s + 2], h2e[8 * s + 3], a3h[s][1], a3l[s][1]);
            split2(h2e[8 * s + 4], h2e[8 * s + 5], a3h[s][2], a3l[s][2]);
            split2(h2e[8 * s + 6], h2e[8 * s + 7], a3h[s][3], a3l[s][3]);
        }

        // GEMM3 in two 5-tile halves with immediate softplus + store of L
        float* o0 = out + (size_t)(warp_s0 + g) * 144;
        float* o8 = out + (size_t)(warp_s0 + g + 8) * 144;
#pragma unroll
        for (int half = 0; half < 2; half++) {
            float acc3[5][4];
#pragma unroll
            for (int j = 0; j < 5; j++) acc3[j][0] = acc3[j][1] = acc3[j][2] = acc3[j][3] = 0.f;
#pragma unroll
            for (int s = 0; s < 2; s++)
#pragma unroll
                for (int j = 0; j < 5; j++)
                    mma3(acc3[j], a3h[s], a3l[s], frag[(48 + 10 * s + 5 * half + j) * 32]);
#pragma unroll
            for (int j = 0; j < 5; j++) {
                int col = 8 * (5 * half + j) + 2 * tq;
                float2 bb = *reinterpret_cast<const float2*>(smf + O_B3 / 4 + col);
                *reinterpret_cast<float2*>(o0 + col) =
                    make_float2(softp(acc3[j][0] + bb.x), softp(acc3[j][1] + bb.y));
                *reinterpret_cast<float2*>(o8 + col) =
                    make_float2(softp(acc3[j][2] + bb.x), softp(acc3[j][3] + bb.y));
            }
        }
    }
}

// =============================== Kernel B ===============================
// Padded-L design: per sample, L scattered into a zero-padded 12x12 lower-tri
// matrix in smem (stride 148 floats/sample = 4*37: vector-aligned AND
// conflict-free). M[r][c] = sum_{j=0..11} Lpad[r][j]*Lpad[c][j] exactly.
// 4 lanes/sample (3 rows each), 8 samples/warp, buffer reused L -> M.

#define BSTR 148                          // floats per sample slot
#define BWARP (8 * BSTR)                  // 1184 floats per warp
#define SMEM_B (4 * BWARP * 4 + 192)      // 19136 B

__global__ void __launch_bounds__(128, 5)
qnc_llt_kernel(float* __restrict__ out)
{
    extern __shared__ float smb[];
    unsigned short* OFF = reinterpret_cast<unsigned short*>(smb + 4 * BWARP);
    const int tid  = threadIdx.x;
    const int lane = tid & 31;
    const int w    = tid >> 5;

    // tri-index f -> padded offset r*12+j (table built once per CTA)
    if (tid < 78) {
        float ff = (float)tid;
        int r = (int)((sqrtf(8.f * ff + 1.f) - 1.f) * 0.5f);
        OFF[tid] = (unsigned short)(r * 12 + tid - (r * (r + 1)) / 2);
    }
    __syncthreads();

    float* buf = smb + w * BWARP;
    const int s0 = blockIdx.x * 32 + w * 8;

    // ---- zero-fill padded region (8 samples x 144 floats) ----
#pragma unroll
    for (int it = 0; it < 9; it++) {
        int q = lane + 32 * it;
        int sq = q / 36, i4 = q % 36;
        *reinterpret_cast<float4*>(&buf[sq * BSTR + 4 * i4]) = make_float4(0.f, 0.f, 0.f, 0.f);
    }
    __syncwarp();

    // ---- coalesced L load + scatter into padded layout ----
#pragma unroll
    for (int it = 0; it < 5; it++) {
        int q = lane + 32 * it;
        int sq = q / 20, i4 = q % 20;
        float4 v = *reinterpret_cast<const float4*>(out + (size_t)(s0 + sq) * 144 + 4 * i4);
        int f = 4 * i4;
        float* bs = buf + sq * BSTR;
        if (f     < 78) bs[OFF[f]]     = v.x;
        if (f + 1 < 78) bs[OFF[f + 1]] = v.y;
        if (f + 2 < 78) bs[OFF[f + 2]] = v.z;
        if (f + 3 < 78) bs[OFF[f + 3]] = v.w;
    }
    __syncwarp();

    // ---- compute: lane (sq, qr) does rows 3qr..3qr+2 of sample sq ----
    const int sq = lane >> 2;
    const int qr = lane & 3;
    const float* Ls = buf + sq * BSTR;

    float a[36];
#pragma unroll
    for (int i = 0; i < 3; i++)
#pragma unroll
        for (int k = 0; k < 3; k++)
            *reinterpret_cast<float4*>(&a[i * 12 + 4 * k]) =
                *reinterpret_cast<const float4*>(&Ls[(3 * qr + i) * 12 + 4 * k]);

    float m[36];
#pragma unroll
    for (int c = 0; c < 12; c++) {
        float bv[12];
#pragma unroll
        for (int k = 0; k < 3; k++)
            *reinterpret_cast<float4*>(&bv[4 * k]) =
                *reinterpret_cast<const float4*>(&Ls[c * 12 + 4 * k]);
#pragma unroll
        for (int i = 0; i < 3; i++) {
            float acc = a[i * 12] * bv[0];
#pragma unroll
            for (int j = 1; j < 12; j++) acc = fmaf(a[i * 12 + j], bv[j], acc);
            m[i * 12 + c] = acc;
        }
    }
    __syncwarp();                          // all Lpad reads done before overwrite

    // ---- store M over the same buffer ----
    float* Ms = buf + sq * BSTR;
#pragma unroll
    for (int i = 0; i < 3; i++)
#pragma unroll
        for (int k = 0; k < 3; k++)
            *reinterpret_cast<float4*>(&Ms[(3 * qr + i) * 12 + 4 * k]) =
                *reinterpret_cast<const float4*>(&m[i * 12 + 4 * k]);
    __syncwarp();

    // ---- coalesced drain ----
#pragma unroll
    for (int it = 0; it < 9; it++) {
        int q = lane + 32 * it;
        int sq2 = q / 36, i4 = q % 36;
        *reinterpret_cast<float4*>(out + (size_t)(s0 + sq2) * 144 + 4 * i4) =
            *reinterpret_cast<const float4*>(&buf[sq2 * BSTR + 4 * i4]);
    }
}

extern "C" void kernel_launch(void* const* d_in, const int* in_sizes, int n_in,
                              void* d_out, int out_size)
{
    const float* x  = (const float*)d_in[0];
    const float* W1 = (const float*)d_in[1];
    const float* b1 = (const float*)d_in[2];
    const float* W2 = (const float*)d_in[3];
    const float* b2 = (const float*)d_in[4];
    const float* W3 = (const float*)d_in[5];
    const float* b3 = (const float*)d_in[6];
    float* out = (float*)d_out;

    const int B = in_sizes[0] / NIN;            // 262144
    const int ntiles = B / 128;                 // 2048 (128 samples per CTA pass)

    cudaFuncSetAttribute(qnc_mlp_kernel, cudaFuncAttributeMaxDynamicSharedMemorySize, SMEM_A);
    cudaFuncSetAttribute(qnc_llt_kernel, cudaFuncAttributeMaxDynamicSharedMemorySize, SMEM_B);

    qnc_mlp_kernel<<<444, 256, SMEM_A>>>(x, W1, b1, W2, b2, W3, b3, out, ntiles);
    qnc_llt_kernel<<<B / 32, 128, SMEM_B>>>(out);
}

// round 9
// speedup vs baseline: 1.0027x; 1.0027x over previous
#include <cuda_runtime.h>
#include <cuda_bf16.h>
#include <cstdint>

// QuadraticNetCholesky, R7: two kernels.
//  A: MLP via mma.sync bf16x3 (unchanged from R6, ~52us), writes L
//     (softplus out, 78+2 floats) into out[s*144+0..79].
//  B: REBUILT. Zero-padded 12x12 L in smem -> uniform 12-deep dots,
//     4 lanes/sample x 3 rows, 8 samples/warp, 20 warps/SM.

#define NIN 12
#define NTILE 68

typedef unsigned int u32;

// ---- kernel A smem (bytes) ----
#define O_FRAG 0                       // 68 tiles x 32 lanes x 16B = 34816
#define O_B2   34816                   // 32 f32
#define O_B3   34944                   // 80 f32
#define SMEM_A (34944 + 320)           // 35264

__device__ __forceinline__ u32 pack_bf16x2(float e0, float e1) {  // e0 -> low half
    u32 d;
    asm("cvt.rn.bf16x2.f32 %0, %1, %2;" : "=r"(d) : "f"(e1), "f"(e0));
    return d;
}
__device__ __forceinline__ void split2(float f0, float f1, u32& hi, u32& lo) {
    hi = pack_bf16x2(f0, f1);
    float h0 = __uint_as_float(hi << 16);
    float h1 = __uint_as_float(hi & 0xffff0000u);
    lo = pack_bf16x2(f0 - h0, f1 - h1);
}
__device__ __forceinline__ float elu_f(float p) { return p > 0.f ? p : (__expf(p) - 1.f); }
__device__ __forceinline__ float softp(float t) {
    return fmaxf(t, 0.f) + __logf(1.f + __expf(-fabsf(t)));
}

__device__ __forceinline__ void mma16816(float* d, u32 a0, u32 a1, u32 a2, u32 a3,
                                         u32 b0, u32 b1) {
    asm volatile(
        "mma.sync.aligned.m16n8k16.row.col.f32.bf16.bf16.f32 "
        "{%0,%1,%2,%3},{%4,%5,%6,%7},{%8,%9},{%0,%1,%2,%3};"
        : "+f"(d[0]), "+f"(d[1]), "+f"(d[2]), "+f"(d[3])
        : "r"(a0), "r"(a1), "r"(a2), "r"(a3), "r"(b0), "r"(b1));
}
__device__ __forceinline__ void mma3(float* d, const u32* ah, const u32* al, uint4 f) {
    mma16816(d, ah[0], ah[1], ah[2], ah[3], f.x, f.y);   // hi*hi
    mma16816(d, ah[0], ah[1], ah[2], ah[3], f.z, f.w);   // hi*lo
    mma16816(d, al[0], al[1], al[2], al[3], f.x, f.y);   // lo*hi
}

// =============================== Kernel A ===============================
__global__ void __launch_bounds__(256, 3)
qnc_mlp_kernel(const float* __restrict__ x,
               const float* __restrict__ W1, const float* __restrict__ b1,
               const float* __restrict__ W2, const float* __restrict__ b2,
               const float* __restrict__ W3, const float* __restrict__ b3,
               float* __restrict__ out, int ntiles)
{
    extern __shared__ char sm[];
    float* smf = reinterpret_cast<float*>(sm);
    const int tid  = threadIdx.x;
    const int lane = tid & 31;
    const int w    = tid >> 5;
    const int g    = lane >> 2;
    const int tq   = lane & 3;

    // ---- stage weights once per CTA in fragment order ----
    for (int idx = tid; idx < NTILE * 32; idx += 256) {
        const int t  = idx >> 5;
        const int l2 = idx & 31;
        const int g2 = l2 >> 2, tq2 = l2 & 3;
        float v0, v1, v2, v3;
        if (t < 16) {                         // W1[128][12] + b1 as K-col 12
            const int n = 8 * t + g2;
            const float* r = W1 + n * NIN;
            v0 = r[2 * tq2]; v1 = r[2 * tq2 + 1];
            const int k2 = 8 + 2 * tq2;
            v2 = (k2 < NIN) ? r[k2] : ((k2 == 12) ? b1[n] : 0.f);
            v3 = (k2 + 1 < NIN) ? r[k2 + 1] : ((k2 + 1 == 12) ? b1[n] : 0.f);
        } else if (t < 48) {                  // W2[32][128]
            const int tt = t - 16, s = tt >> 2, j = tt & 3;
            const float* r = W2 + (8 * j + g2) * 128 + 16 * s;
            v0 = r[2 * tq2]; v1 = r[2 * tq2 + 1];
            v2 = r[8 + 2 * tq2]; v3 = r[9 + 2 * tq2];
        } else {                              // W3[78][32], rows 78,79 = 0
            const int tt = t - 48, s = tt / 10, j = tt - 10 * s;
            const int n = 8 * j + g2;
            if (n < 78) {
                const float* r = W3 + n * 32 + 16 * s;
                v0 = r[2 * tq2]; v1 = r[2 * tq2 + 1];
                v2 = r[8 + 2 * tq2]; v3 = r[9 + 2 * tq2];
            } else {
                v0 = v1 = v2 = v3 = 0.f;
            }
        }
        u32 h0, l0, h1, l1;
        split2(v0, v1, h0, l0);
        split2(v2, v3, h1, l1);
        *reinterpret_cast<uint4*>(sm + O_FRAG + t * 512 + l2 * 16) =
            make_uint4(h0, h1, l0, l1);
    }
    for (int i = tid; i < 32; i += 256) smf[O_B2 / 4 + i] = b2[i];
    for (int i = tid; i < 80; i += 256) smf[O_B3 / 4 + i] = (i < 78) ? b3[i] : 0.f;
    __syncthreads();

    const uint4* frag = reinterpret_cast<const uint4*>(sm + O_FRAG) + lane;

    for (int tile = blockIdx.x; tile < ntiles; tile += gridDim.x) {
        const int warp_s0 = tile * 128 + w * 16;

        // A1 fragments from x
        const float* xr  = x + (size_t)(warp_s0 + g) * NIN;
        const float* xr8 = xr + 8 * NIN;
        float2 xa = *reinterpret_cast<const float2*>(xr  + 2 * tq);
        float2 xb = *reinterpret_cast<const float2*>(xr8 + 2 * tq);
        float2 xc, xd;
        if (tq < 2) {
            xc = *reinterpret_cast<const float2*>(xr  + 8 + 2 * tq);
            xd = *reinterpret_cast<const float2*>(xr8 + 8 + 2 * tq);
        } else {
            float one = (tq == 2) ? 1.f : 0.f;    // bias col 12
            xc = make_float2(one, 0.f);
            xd = make_float2(one, 0.f);
        }
        u32 a1h[4], a1l[4];
        split2(xa.x, xa.y, a1h[0], a1l[0]);
        split2(xb.x, xb.y, a1h[1], a1l[1]);
        split2(xc.x, xc.y, a1h[2], a1l[2]);
        split2(xd.x, xd.y, a1h[3], a1l[3]);

        // fused GEMM1 -> elu -> GEMM2, one k-step (16 h1 neurons) at a time
        float acc2[4][4];
#pragma unroll
        for (int j = 0; j < 4; j++) acc2[j][0] = acc2[j][1] = acc2[j][2] = acc2[j][3] = 0.f;
#pragma unroll
        for (int s = 0; s < 8; s++) {
            float p[8];
#pragma unroll
            for (int q = 0; q < 8; q++) p[q] = 0.f;
            mma3(p,     a1h, a1l, frag[(2 * s) * 32]);
            mma3(p + 4, a1h, a1l, frag[(2 * s + 1) * 32]);
            u32 a2h4[4], a2l4[4];
            split2(elu_f(p[0]), elu_f(p[1]), a2h4[0], a2l4[0]);
            split2(elu_f(p[2]), elu_f(p[3]), a2h4[1], a2l4[1]);
            split2(elu_f(p[4]), elu_f(p[5]), a2h4[2], a2l4[2]);
            split2(elu_f(p[6]), elu_f(p[7]), a2h4[3], a2l4[3]);
#pragma unroll
            for (int j = 0; j < 4; j++)
                mma3(acc2[j], a2h4, a2l4, frag[(16 + 4 * s + j) * 32]);
        }

        // epi2: +b2, elu -> A3 fragments
        float h2e[16];
#pragma unroll
        for (int j = 0; j < 4; j++) {
            float2 bb = *reinterpret_cast<const float2*>(smf + O_B2 / 4 + 8 * j + 2 * tq);
            h2e[4 * j + 0] = elu_f(acc2[j][0] + bb.x);
            h2e[4 * j + 1] = elu_f(acc2[j][1] + bb.y);
            h2e[4 * j + 2] = elu_f(acc2[j][2] + bb.x);
            h2e[4 * j + 3] = elu_f(acc2[j][3] + bb.y);
        }
        u32 a3h[2][4], a3l[2][4];
#pragma unroll
        for (int s = 0; s < 2; s++) {
            split2(h2e[8 * s + 0], h2e[8 * s + 1], a3h[s][0], a3l[s][0]);
            split2(h2e[8 * s + 2], h2e[8 * s + 3], a3h[s][1], a3l[s][1]);
            split2(h2e[8 * s + 4], h2e[8 * s + 5], a3h[s][2], a3l[s][2]);
            split2(h2e[8 * s + 6], h2e[8 * s + 7], a3h[s][3], a3l[s][3]);
        }

        // GEMM3 in two 5-tile halves with immediate softplus + store of L
        float* o0 = out + (size_t)(warp_s0 + g) * 144;
        float* o8 = out + (size_t)(warp_s0 + g + 8) * 144;
#pragma unroll
        for (int half = 0; half < 2; half++) {
            float acc3[5][4];
#pragma unroll
            for (int j = 0; j < 5; j++) acc3[j][0] = acc3[j][1] = acc3[j][2] = acc3[j][3] = 0.f;
#pragma unroll
            for (int s = 0; s < 2; s++)
#pragma unroll
                for (int j = 0; j < 5; j++)
                    mma3(acc3[j], a3h[s], a3l[s], frag[(48 + 10 * s + 5 * half + j) * 32]);
#pragma unroll
            for (int j = 0; j < 5; j++) {
                int col = 8 * (5 * half + j) + 2 * tq;
                float2 bb = *reinterpret_cast<const float2*>(smf + O_B3 / 4 + col);
                *reinterpret_cast<float2*>(o0 + col) =
                    make_float2(softp(acc3[j][0] + bb.x), softp(acc3[j][1] + bb.y));
                *reinterpret_cast<float2*>(o8 + col) =
                    make_float2(softp(acc3[j][2] + bb.x), softp(acc3[j][3] + bb.y));
            }
        }
    }
}

// =============================== Kernel B ===============================
// Padded-L design: per sample, L scattered into a zero-padded 12x12 lower-tri
// matrix in smem (stride 148 floats/sample = 4*37: vector-aligned AND
// conflict-free). M[r][c] = sum_{j=0..11} Lpad[r][j]*Lpad[c][j] exactly.
// 4 lanes/sample (3 rows each), 8 samples/warp, buffer reused L -> M.

#define BSTR 148                          // floats per sample slot
#define BWARP (8 * BSTR)                  // 1184 floats per warp
#define SMEM_B (4 * BWARP * 4 + 192)      // 19136 B

__global__ void __launch_bounds__(128, 5)
qnc_llt_kernel(float* __restrict__ out)
{
    extern __shared__ float smb[];
    unsigned short* OFF = reinterpret_cast<unsigned short*>(smb + 4 * BWARP);
    const int tid  = threadIdx.x;
    const int lane = tid & 31;
    const int w    = tid >> 5;

    // tri-index f -> padded offset r*12+j (table built once per CTA)
    if (tid < 78) {
        float ff = (float)tid;
        int r = (int)((sqrtf(8.f * ff + 1.f) - 1.f) * 0.5f);
        OFF[tid] = (unsigned short)(r * 12 + tid - (r * (r + 1)) / 2);
    }
    __syncthreads();

    float* buf = smb + w * BWARP;
    const int s0 = blockIdx.x * 32 + w * 8;

    // ---- zero-fill padded region (8 samples x 144 floats) ----
#pragma unroll
    for (int it = 0; it < 9; it++) {
        int q = lane + 32 * it;
        int sq = q / 36, i4 = q % 36;
        *reinterpret_cast<float4*>(&buf[sq * BSTR + 4 * i4]) = make_float4(0.f, 0.f, 0.f, 0.f);
    }
    __syncwarp();

    // ---- coalesced L load + scatter into padded layout ----
#pragma unroll
    for (int it = 0; it < 5; it++) {
        int q = lane + 32 * it;
        int sq = q / 20, i4 = q % 20;
        float4 v = *reinterpret_cast<const float4*>(out + (size_t)(s0 + sq) * 144 + 4 * i4);
        int f = 4 * i4;
        float* bs = buf + sq * BSTR;
        if (f     < 78) bs[OFF[f]]     = v.x;
        if (f + 1 < 78) bs[OFF[f + 1]] = v.y;
        if (f + 2 < 78) bs[OFF[f + 2]] = v.z;
        if (f + 3 < 78) bs[OFF[f + 3]] = v.w;
    }
    __syncwarp();

    // ---- compute: lane (sq, qr) does rows 3qr..3qr+2 of sample sq ----
    const int sq = lane >> 2;
    const int qr = lane & 3;
    const float* Ls = buf + sq * BSTR;

    float a[36];
#pragma unroll
    for (int i = 0; i < 3; i++)
#pragma unroll
        for (int k = 0; k < 3; k++)
            *reinterpret_cast<float4*>(&a[i * 12 + 4 * k]) =
                *reinterpret_cast<const float4*>(&Ls[(3 * qr + i) * 12 + 4 * k]);

    float m[36];
#pragma unroll
    for (int c = 0; c < 12; c++) {
        float bv[12];
#pragma unroll
        for (int k = 0; k < 3; k++)
            *reinterpret_cast<float4*>(&bv[4 * k]) =
                *reinterpret_cast<const float4*>(&Ls[c * 12 + 4 * k]);
#pragma unroll
        for (int i = 0; i < 3; i++) {
            float acc = a[i * 12] * bv[0];
#pragma unroll
            for (int j = 1; j < 12; j++) acc = fmaf(a[i * 12 + j], bv[j], acc);
            m[i * 12 + c] = acc;
        }
    }
    __syncwarp();                          // all Lpad reads done before overwrite

    // ---- store M over the same buffer ----
    float* Ms = buf + sq * BSTR;
#pragma unroll
    for (int i = 0; i < 3; i++)
#pragma unroll
        for (int k = 0; k < 3; k++)
            *reinterpret_cast<float4*>(&Ms[(3 * qr + i) * 12 + 4 * k]) =
                *reinterpret_cast<const float4*>(&m[i * 12 + 4 * k]);
    __syncwarp();

    // ---- coalesced drain ----
#pragma unroll
    for (int it = 0; it < 9; it++) {
        int q = lane + 32 * it;
        int sq2 = q / 36, i4 = q % 36;
        *reinterpret_cast<float4*>(out + (size_t)(s0 + sq2) * 144 + 4 * i4) =
            *reinterpret_cast<const float4*>(&buf[sq2 * BSTR + 4 * i4]);
    }
}

extern "C" void kernel_launch(void* const* d_in, const int* in_sizes, int n_in,
                              void* d_out, int out_size)
{
    const float* x  = (const float*)d_in[0];
    const float* W1 = (const float*)d_in[1];
    const float* b1 = (const float*)d_in[2];
    const float* W2 = (const float*)d_in[3];
    const float* b2 = (const float*)d_in[4];
    const float* W3 = (const float*)d_in[5];
    const float* b3 = (const float*)d_in[6];
    float* out = (float*)d_out;

    const int B = in_sizes[0] / NIN;            // 262144
    const int ntiles = B / 128;                 // 2048 (128 samples per CTA pass)

    cudaFuncSetAttribute(qnc_mlp_kernel, cudaFuncAttributeMaxDynamicSharedMemorySize, SMEM_A);
    cudaFuncSetAttribute(qnc_llt_kernel, cudaFuncAttributeMaxDynamicSharedMemorySize, SMEM_B);

    qnc_mlp_kernel<<<444, 256, SMEM_A>>>(x, W1, b1, W2, b2, W3, b3, out, ntiles);
    qnc_llt_kernel<<<B / 32, 128, SMEM_B>>>(out);
}

// round 10
// speedup vs baseline: 1.0035x; 1.0008x over previous
#include <cuda_runtime.h>
#include <cuda_bf16.h>
#include <cstdint>

// QuadraticNetCholesky, R7: two kernels.
//  A: MLP via mma.sync bf16x3 (unchanged from R6, ~52us), writes L
//     (softplus out, 78+2 floats) into out[s*144+0..79].
//  B: REBUILT. Zero-padded 12x12 L in smem -> uniform 12-deep dots,
//     4 lanes/sample x 3 rows, 8 samples/warp, 20 warps/SM.

#define NIN 12
#define NTILE 68

typedef unsigned int u32;

// ---- kernel A smem (bytes) ----
#define O_FRAG 0                       // 68 tiles x 32 lanes x 16B = 34816
#define O_B2   34816                   // 32 f32
#define O_B3   34944                   // 80 f32
#define SMEM_A (34944 + 320)           // 35264

__device__ __forceinline__ u32 pack_bf16x2(float e0, float e1) {  // e0 -> low half
    u32 d;
    asm("cvt.rn.bf16x2.f32 %0, %1, %2;" : "=r"(d) : "f"(e1), "f"(e0));
    return d;
}
__device__ __forceinline__ void split2(float f0, float f1, u32& hi, u32& lo) {
    hi = pack_bf16x2(f0, f1);
    float h0 = __uint_as_float(hi << 16);
    float h1 = __uint_as_float(hi & 0xffff0000u);
    lo = pack_bf16x2(f0 - h0, f1 - h1);
}
__device__ __forceinline__ float elu_f(float p) { return p > 0.f ? p : (__expf(p) - 1.f); }
__device__ __forceinline__ float softp(float t) {
    return fmaxf(t, 0.f) + __logf(1.f + __expf(-fabsf(t)));
}

__device__ __forceinline__ void mma16816(float* d, u32 a0, u32 a1, u32 a2, u32 a3,
                                         u32 b0, u32 b1) {
    asm volatile(
        "mma.sync.aligned.m16n8k16.row.col.f32.bf16.bf16.f32 "
        "{%0,%1,%2,%3},{%4,%5,%6,%7},{%8,%9},{%0,%1,%2,%3};"
        : "+f"(d[0]), "+f"(d[1]), "+f"(d[2]), "+f"(d[3])
        : "r"(a0), "r"(a1), "r"(a2), "r"(a3), "r"(b0), "r"(b1));
}
__device__ __forceinline__ void mma3(float* d, const u32* ah, const u32* al, uint4 f) {
    mma16816(d, ah[0], ah[1], ah[2], ah[3], f.x, f.y);   // hi*hi
    mma16816(d, ah[0], ah[1], ah[2], ah[3], f.z, f.w);   // hi*lo
    mma16816(d, al[0], al[1], al[2], al[3], f.x, f.y);   // lo*hi
}

// =============================== Kernel A ===============================
__global__ void __launch_bounds__(256, 3)
qnc_mlp_kernel(const float* __restrict__ x,
               const float* __restrict__ W1, const float* __restrict__ b1,
               const float* __restrict__ W2, const float* __restrict__ b2,
               const float* __restrict__ W3, const float* __restrict__ b3,
               float* __restrict__ out, int ntiles)
{
    extern __shared__ char sm[];
    float* smf = reinterpret_cast<float*>(sm);
    const int tid  = threadIdx.x;
    const int lane = tid & 31;
    const int w    = tid >> 5;
    const int g    = lane >> 2;
    const int tq   = lane & 3;

    // ---- stage weights once per CTA in fragment order ----
    for (int idx = tid; idx < NTILE * 32; idx += 256) {
        const int t  = idx >> 5;
        const int l2 = idx & 31;
        const int g2 = l2 >> 2, tq2 = l2 & 3;
        float v0, v1, v2, v3;
        if (t < 16) {                         // W1[128][12] + b1 as K-col 12
            const int n = 8 * t + g2;
            const float* r = W1 + n * NIN;
            v0 = r[2 * tq2]; v1 = r[2 * tq2 + 1];
            const int k2 = 8 + 2 * tq2;
            v2 = (k2 < NIN) ? r[k2] : ((k2 == 12) ? b1[n] : 0.f);
            v3 = (k2 + 1 < NIN) ? r[k2 + 1] : ((k2 + 1 == 12) ? b1[n] : 0.f);
        } else if (t < 48) {                  // W2[32][128]
            const int tt = t - 16, s = tt >> 2, j = tt & 3;
            const float* r = W2 + (8 * j + g2) * 128 + 16 * s;
            v0 = r[2 * tq2]; v1 = r[2 * tq2 + 1];
            v2 = r[8 + 2 * tq2]; v3 = r[9 + 2 * tq2];
        } else {                              // W3[78][32], rows 78,79 = 0
            const int tt = t - 48, s = tt / 10, j = tt - 10 * s;
            const int n = 8 * j + g2;
            if (n < 78) {
                const float* r = W3 + n * 32 + 16 * s;
                v0 = r[2 * tq2]; v1 = r[2 * tq2 + 1];
                v2 = r[8 + 2 * tq2]; v3 = r[9 + 2 * tq2];
            } else {
                v0 = v1 = v2 = v3 = 0.f;
            }
        }
        u32 h0, l0, h1, l1;
        split2(v0, v1, h0, l0);
        split2(v2, v3, h1, l1);
        *reinterpret_cast<uint4*>(sm + O_FRAG + t * 512 + l2 * 16) =
            make_uint4(h0, h1, l0, l1);
    }
    for (int i = tid; i < 32; i += 256) smf[O_B2 / 4 + i] = b2[i];
    for (int i = tid; i < 80; i += 256) smf[O_B3 / 4 + i] = (i < 78) ? b3[i] : 0.f;
    __syncthreads();

    const uint4* frag = reinterpret_cast<const uint4*>(sm + O_FRAG) + lane;

    for (int tile = blockIdx.x; tile < ntiles; tile += gridDim.x) {
        const int warp_s0 = tile * 128 + w * 16;

        // A1 fragments from x
        const float* xr  = x + (size_t)(warp_s0 + g) * NIN;
        const float* xr8 = xr + 8 * NIN;
        float2 xa = *reinterpret_cast<const float2*>(xr  + 2 * tq);
        float2 xb = *reinterpret_cast<const float2*>(xr8 + 2 * tq);
        float2 xc, xd;
        if (tq < 2) {
            xc = *reinterpret_cast<const float2*>(xr  + 8 + 2 * tq);
            xd = *reinterpret_cast<const float2*>(xr8 + 8 + 2 * tq);
        } else {
            float one = (tq == 2) ? 1.f : 0.f;    // bias col 12
            xc = make_float2(one, 0.f);
            xd = make_float2(one, 0.f);
        }
        u32 a1h[4], a1l[4];
        split2(xa.x, xa.y, a1h[0], a1l[0]);
        split2(xb.x, xb.y, a1h[1], a1l[1]);
        split2(xc.x, xc.y, a1h[2], a1l[2]);
        split2(xd.x, xd.y, a1h[3], a1l[3]);

        // fused GEMM1 -> elu -> GEMM2, one k-step (16 h1 neurons) at a time
        float acc2[4][4];
#pragma unroll
        for (int j = 0; j < 4; j++) acc2[j][0] = acc2[j][1] = acc2[j][2] = acc2[j][3] = 0.f;
#pragma unroll
        for (int s = 0; s < 8; s++) {
            float p[8];
#pragma unroll
            for (int q = 0; q < 8; q++) p[q] = 0.f;
            mma3(p,     a1h, a1l, frag[(2 * s) * 32]);
            mma3(p + 4, a1h, a1l, frag[(2 * s + 1) * 32]);
            u32 a2h4[4], a2l4[4];
            split2(elu_f(p[0]), elu_f(p[1]), a2h4[0], a2l4[0]);
            split2(elu_f(p[2]), elu_f(p[3]), a2h4[1], a2l4[1]);
            split2(elu_f(p[4]), elu_f(p[5]), a2h4[2], a2l4[2]);
            split2(elu_f(p[6]), elu_f(p[7]), a2h4[3], a2l4[3]);
#pragma unroll
            for (int j = 0; j < 4; j++)
                mma3(acc2[j], a2h4, a2l4, frag[(16 + 4 * s + j) * 32]);
        }

        // epi2: +b2, elu -> A3 fragments
        float h2e[16];
#pragma unroll
        for (int j = 0; j < 4; j++) {
            float2 bb = *reinterpret_cast<const float2*>(smf + O_B2 / 4 + 8 * j + 2 * tq);
            h2e[4 * j + 0] = elu_f(acc2[j][0] + bb.x);
            h2e[4 * j + 1] = elu_f(acc2[j][1] + bb.y);
            h2e[4 * j + 2] = elu_f(acc2[j][2] + bb.x);
            h2e[4 * j + 3] = elu_f(acc2[j][3] + bb.y);
        }
        u32 a3h[2][4], a3l[2][4];
#pragma unroll
        for (int s = 0; s < 2; s++) {
            split2(h2e[8 * s + 0], h2e[8 * s + 1], a3h[s][0], a3l[s][0]);
            split2(h2e[8 * s + 2], h2e[8 * s + 3], a3h[s][1], a3l[s][1]);
            split2(h2e[8 * s + 4], h2e[8 * s + 5], a3h[s][2], a3l[s][2]);
            split2(h2e[8 * s + 6], h2e[8 * s + 7], a3h[s][3], a3l[s][3]);
        }

        // GEMM3 in two 5-tile halves with immediate softplus + store of L
        float* o0 = out + (size_t)(warp_s0 + g) * 144;
        float* o8 = out + (size_t)(warp_s0 + g + 8) * 144;
#pragma unroll
        for (int half = 0; half < 2; half++) {
            float acc3[5][4];
#pragma unroll
            for (int j = 0; j < 5; j++) acc3[j][0] = acc3[j][1] = acc3[j][2] = acc3[j][3] = 0.f;
#pragma unroll
            for (int s = 0; s < 2; s++)
#pragma unroll
                for (int j = 0; j < 5; j++)
                    mma3(acc3[j], a3h[s], a3l[s], frag[(48 + 10 * s + 5 * half + j) * 32]);
#pragma unroll
            for (int j = 0; j < 5; j++) {
                int col = 8 * (5 * half + j) + 2 * tq;
                float2 bb = *reinterpret_cast<const float2*>(smf + O_B3 / 4 + col);
                *reinterpret_cast<float2*>(o0 + col) =
                    make_float2(softp(acc3[j][0] + bb.x), softp(acc3[j][1] + bb.y));
                *reinterpret_cast<float2*>(o8 + col) =
                    make_float2(softp(acc3[j][2] + bb.x), softp(acc3[j][3] + bb.y));
            }
        }
    }
}

// =============================== Kernel B ===============================
// Padded-L design: per sample, L scattered into a zero-padded 12x12 lower-tri
// matrix in smem (stride 148 floats/sample = 4*37: vector-aligned AND
// conflict-free). M[r][c] = sum_{j=0..11} Lpad[r][j]*Lpad[c][j] exactly.
// 4 lanes/sample (3 rows each), 8 samples/warp, buffer reused L -> M.

#define BSTR 148                          // floats per sample slot
#define BWARP (8 * BSTR)                  // 1184 floats per warp
#define SMEM_B (4 * BWARP * 4 + 192)      // 19136 B

__global__ void __launch_bounds__(128, 5)
qnc_llt_kernel(float* __restrict__ out)
{
    extern __shared__ float smb[];
    unsigned short* OFF = reinterpret_cast<unsigned short*>(smb + 4 * BWARP);
    const int tid  = threadIdx.x;
    const int lane = tid & 31;
    const int w    = tid >> 5;

    // tri-index f -> padded offset r*12+j (table built once per CTA)
    if (tid < 78) {
        float ff = (float)tid;
        int r = (int)((sqrtf(8.f * ff + 1.f) - 1.f) * 0.5f);
        OFF[tid] = (unsigned short)(r * 12 + tid - (r * (r + 1)) / 2);
    }
    __syncthreads();

    float* buf = smb + w * BWARP;
    const int s0 = blockIdx.x * 32 + w * 8;

    // ---- zero-fill padded region (8 samples x 144 floats) ----
#pragma unroll
    for (int it = 0; it < 9; it++) {
        int q = lane + 32 * it;
        int sq = q / 36, i4 = q % 36;
        *reinterpret_cast<float4*>(&buf[sq * BSTR + 4 * i4]) = make_float4(0.f, 0.f, 0.f, 0.f);
    }
    __syncwarp();

    // ---- coalesced L load + scatter into padded layout ----
#pragma unroll
    for (int it = 0; it < 5; it++) {
        int q = lane + 32 * it;
        int sq = q / 20, i4 = q % 20;
        float4 v = *reinterpret_cast<const float4*>(out + (size_t)(s0 + sq) * 144 + 4 * i4);
        int f = 4 * i4;
        float* bs = buf + sq * BSTR;
        if (f     < 78) bs[OFF[f]]     = v.x;
        if (f + 1 < 78) bs[OFF[f + 1]] = v.y;
        if (f + 2 < 78) bs[OFF[f + 2]] = v.z;
        if (f + 3 < 78) bs[OFF[f + 3]] = v.w;
    }
    __syncwarp();

    // ---- compute: lane (sq, qr) does rows 3qr..3qr+2 of sample sq ----
    const int sq = lane >> 2;
    const int qr = lane & 3;
    const float* Ls = buf + sq * BSTR;

    float a[36];
#pragma unroll
    for (int i = 0; i < 3; i++)
#pragma unroll
        for (int k = 0; k < 3; k++)
            *reinterpret_cast<float4*>(&a[i * 12 + 4 * k]) =
                *reinterpret_cast<const float4*>(&Ls[(3 * qr + i) * 12 + 4 * k]);

    float m[36];
#pragma unroll
    for (int c = 0; c < 12; c++) {
        float bv[12];
#pragma unroll
        for (int k = 0; k < 3; k++)
            *reinterpret_cast<float4*>(&bv[4 * k]) =
                *reinterpret_cast<const float4*>(&Ls[c * 12 + 4 * k]);
#pragma unroll
        for (int i = 0; i < 3; i++) {
            float acc = a[i * 12] * bv[0];
#pragma unroll
            for (int j = 1; j < 12; j++) acc = fmaf(a[i * 12 + j], bv[j], acc);
            m[i * 12 + c] = acc;
        }
    }
    __syncwarp();                          // all Lpad reads done before overwrite

    // ---- store M over the same buffer ----
    float* Ms = buf + sq * BSTR;
#pragma unroll
    for (int i = 0; i < 3; i++)
#pragma unroll
        for (int k = 0; k < 3; k++)
            *reinterpret_cast<float4*>(&Ms[(3 * qr + i) * 12 + 4 * k]) =
                *reinterpret_cast<const float4*>(&m[i * 12 + 4 * k]);
    __syncwarp();

    // ---- coalesced drain ----
#pragma unroll
    for (int it = 0; it < 9; it++) {
        int q = lane + 32 * it;
        int sq2 = q / 36, i4 = q % 36;
        *reinterpret_cast<float4*>(out + (size_t)(s0 + sq2) * 144 + 4 * i4) =
            *reinterpret_cast<const float4*>(&buf[sq2 * BSTR + 4 * i4]);
    }
}

extern "C" void kernel_launch(void* const* d_in, const int* in_sizes, int n_in,
                              void* d_out, int out_size)
{
    const float* x  = (const float*)d_in[0];
    const float* W1 = (const float*)d_in[1];
    const float* b1 = (const float*)d_in[2];
    const float* W2 = (const float*)d_in[3];
    const float* b2 = (const float*)d_in[4];
    const float* W3 = (const float*)d_in[5];
    const float* b3 = (const float*)d_in[6];
    float* out = (float*)d_out;

    const int B = in_sizes[0] / NIN;            // 262144
    const int ntiles = B / 128;                 // 2048 (128 samples per CTA pass)

    cudaFuncSetAttribute(qnc_mlp_kernel, cudaFuncAttributeMaxDynamicSharedMemorySize, SMEM_A);
    cudaFuncSetAttribute(qnc_llt_kernel, cudaFuncAttributeMaxDynamicSharedMemorySize, SMEM_B);

    qnc_mlp_kernel<<<444, 256, SMEM_A>>>(x, W1, b1, W2, b2, W3, b3, out, ntiles);
    qnc_llt_kernel<<<B / 32, 128, SMEM_B>>>(out);
}